// round 12
// baseline (speedup 1.0000x reference)
#include <cuda_runtime.h>
#include <cstdint>

// ---------------------------------------------------------------------------
// Problem constants
//   B=8, CIN=16, HID=64, T=4, W=32, H=32, TAU=5
//   SP  = T*W*H          = 4096
//   CSP = HID*SP         = 262144      (one batch slice of a state tensor)
//   VOL = B*CSP          = 2097152     (one full state tensor)
// Output layout (flattened tuple): c_history_new[5*VOL], m_new[VOL], h_new[VOL]
// ---------------------------------------------------------------------------
#define SP   4096
#define CSP  262144
#define VOL  2097152
#define EPSF 1e-5f

// Scratch (device globals -- no allocation allowed in kernel_launch)
__device__ float g_u[7u * (unsigned)VOL];   // u0..u5 gate pre/post-acts, u6 = o-branch
__device__ float g_wxT[7 * 16 * 27 * 64];   // Wx transposed to [k][ci][tap][co]
__device__ float g_whT[9 * 64 * 27 * 64];   // Wh transposed to [k][ci][tap][co]
__device__ float g_w111T[128 * 64];         // w111 transposed to [ci][co]
__device__ float g_scores[40];              // [l][b]
__device__ float g_attn[40];                // [l][b]
__device__ float g_part[2048 * 2];          // per-block (sum, sumsq) partials for LN4
__device__ float g_stats[16];               // per-b (sum, sumsq) for LN4

// ---------------------------------------------------------------------------
// helpers
// ---------------------------------------------------------------------------
__device__ __forceinline__ void block_reduce2(float& a, float& b, float* sh) {
    const int lane = threadIdx.x & 31, wid = threadIdx.x >> 5;
#pragma unroll
    for (int o = 16; o; o >>= 1) {
        a += __shfl_down_sync(0xffffffffu, a, o);
        b += __shfl_down_sync(0xffffffffu, b, o);
    }
    if (lane == 0) { sh[wid] = a; sh[8 + wid] = b; }
    __syncthreads();
    if (wid == 0) {
        a = lane < 8 ? sh[lane] : 0.f;
        b = lane < 8 ? sh[8 + lane] : 0.f;
#pragma unroll
        for (int o = 4; o; o >>= 1) {
            a += __shfl_down_sync(0xffffffffu, a, o);
            b += __shfl_down_sync(0xffffffffu, b, o);
        }
        if (lane == 0) { sh[0] = a; sh[8] = b; }
    }
    __syncthreads();
    a = sh[0]; b = sh[8];
}

// ---------------------------------------------------------------------------
// Core 3x3x3 'same' conv accumulation over CI input channels into 32 f32x2
// accumulators (64 output channels, pair-packed). Block covers one (b, t0,
// 8-row w slice) for all 64 co. Weights must be pre-transposed [ci][tap][co].
// ---------------------------------------------------------------------------
__device__ __forceinline__ void conv_accum(
    const float* __restrict__ in,   // [CI][4][32][32] (b offset already applied)
    const float* __restrict__ wT,   // [CI][27][64]
    int CI, int t0, int wbase,
    float* s_in,                    // [3*10*34]
    float* s_w,                     // [27*64]
    unsigned long long* acc)        // [32]
{
    const int tid = threadIdx.x;
    const int wl = tid >> 5, hh = tid & 31;
    for (int ci = 0; ci < CI; ++ci) {
        __syncthreads();   // previous compute done before smem overwrite
        const float* ip = in + ci * SP;
#pragma unroll
        for (int u = 0; u < 4; ++u) {
            int idx = tid + u * 256;
            if (idx < 1020) {
                int dt = idx / 340;
                int rem = idx - dt * 340;
                int row = rem / 34;
                int col = rem - row * 34;
                int tt = t0 + dt - 1, ww = wbase + row - 1, ch = col - 1;
                float v = 0.f;
                if (((unsigned)tt < 4u) & ((unsigned)ww < 32u) & ((unsigned)ch < 32u))
                    v = ip[tt * 1024 + ww * 32 + ch];
                s_in[idx] = v;
            }
        }
        const float* wp = wT + ci * 1728;
#pragma unroll
        for (int u = 0; u < 7; ++u) {
            int idx = tid + u * 256;
            if (idx < 1728) s_w[idx] = wp[idx];
        }
        __syncthreads();
#pragma unroll
        for (int dt = 0; dt < 3; ++dt)
#pragma unroll
        for (int dw = 0; dw < 3; ++dw)
#pragma unroll
        for (int dh = 0; dh < 3; ++dh) {
            float v = s_in[(dt * 10 + wl + dw) * 34 + hh + dh];
            unsigned long long vv;
            asm("mov.b64 %0, {%1, %1};" : "=l"(vv) : "f"(v));
            const unsigned long long* wq =
                reinterpret_cast<const unsigned long long*>(s_w + (dt * 9 + dw * 3 + dh) * 64);
#pragma unroll
            for (int cp = 0; cp < 32; ++cp)
                asm("fma.rn.f32x2 %0, %1, %2, %0;" : "+l"(acc[cp]) : "l"(vv), "l"(wq[cp]));
        }
    }
}

// ---------------------------------------------------------------------------
// prep: transpose weights into coalesced-load layouts
// ---------------------------------------------------------------------------
__global__ void prep_kernel(const float* __restrict__ Wx,
                            const float* __restrict__ Wh,
                            const float* __restrict__ w111) {
    int idx = blockIdx.x * 256 + threadIdx.x;
    if (idx < 193536) {                         // Wx: [7][64][16][27] -> [7][16][27][64]
        int co = idx & 63; int q = idx >> 6;
        int tap = q % 27;  int q2 = q / 27;
        int ci = q2 & 15;  int k = q2 >> 4;
        g_wxT[idx] = Wx[((k * 64 + co) * 16 + ci) * 27 + tap];
    } else if (idx < 1188864) {                 // Wh: [9][64][64][27] -> [9][64][27][64]
        int j = idx - 193536;
        int co = j & 63; int q = j >> 6;
        int tap = q % 27; int q2 = q / 27;
        int ci = q2 & 63; int k = q2 >> 6;
        g_whT[j] = Wh[((k * 64 + co) * 64 + ci) * 27 + tap];
    } else if (idx < 1197056) {                 // w111: [64][128] -> [128][64]
        int j = idx - 1188864;
        int co = j & 63; int ci = j >> 6;
        g_w111T[j] = w111[co * 128 + ci];
    }
}

// ---------------------------------------------------------------------------
// stage1: u_k = conv(x, Wx[k]) + conv(state_k, Wh[k]) + bx[k] + bh[k], k=0..6
//   state: k in {0,1,2,6} -> h ;  k in {3,4,5} -> m
// grid (4 wtiles, 4 t, 56 = k*8+b), 256 threads
// ---------------------------------------------------------------------------
__global__ void __launch_bounds__(256, 2)
stage1_kernel(const float* __restrict__ x, const float* __restrict__ h,
              const float* __restrict__ m, const float* __restrict__ bx,
              const float* __restrict__ bh) {
    __shared__ __align__(16) float s_in[1020];
    __shared__ __align__(16) float s_w[1728];
    const int b = blockIdx.z & 7, k = blockIdx.z >> 3;
    const int t0 = blockIdx.y, wbase = blockIdx.x * 8;
    unsigned long long acc[32];
#pragma unroll
    for (int i = 0; i < 32; ++i) acc[i] = 0ull;

    conv_accum(x + (size_t)b * 16 * SP, g_wxT + k * 27648, 16, t0, wbase, s_in, s_w, acc);
    const float* st = (k < 3 || k == 6) ? h : m;
    conv_accum(st + (size_t)b * CSP, g_whT + k * 110592, 64, t0, wbase, s_in, s_w, acc);

    const int tid = threadIdx.x;
    const int wl = tid >> 5, hh = tid & 31;
    float* up = g_u + (size_t)k * VOL + (size_t)b * CSP + t0 * 1024 + (wbase + wl) * 32 + hh;
#pragma unroll
    for (int cp = 0; cp < 32; ++cp) {
        float lo, hi;
        asm("mov.b64 {%0, %1}, %2;" : "=f"(lo), "=f"(hi) : "l"(acc[cp]));
        int co = 2 * cp;
        up[(size_t)co * SP]       = lo + bx[k * 64 + co]     + bh[k * 64 + co];
        up[(size_t)(co + 1) * SP] = hi + bx[k * 64 + co + 1] + bh[k * 64 + co + 1];
    }
}

// ---------------------------------------------------------------------------
// LN3 (per (b,co), over 4096 spatial) + activation, in place on g_u[k]
//   k in {2,4} -> tanh, else sigmoid. grid (512, nk), kbase arg.
// ---------------------------------------------------------------------------
__global__ void ln3_act_kernel(int kbase) {
    __shared__ float sh[16];
    const int k = kbase + blockIdx.y;
    float* buf = g_u + (size_t)k * VOL + (size_t)blockIdx.x * SP;
    const int tid = threadIdx.x;
    float v[16], s = 0.f, sq = 0.f;
#pragma unroll
    for (int j = 0; j < 16; ++j) {
        v[j] = buf[tid + j * 256];
        s += v[j]; sq += v[j] * v[j];
    }
    block_reduce2(s, sq, sh);
    const float mu = s * (1.f / 4096.f);
    const float var = sq * (1.f / 4096.f) - mu * mu;
    const float rstd = rsqrtf(var + EPSF);
    const bool ist = (k == 2 || k == 4);
#pragma unroll
    for (int j = 0; j < 16; ++j) {
        float y = (v[j] - mu) * rstd;
        buf[tid + j * 256] = ist ? tanhf(y) : (1.f / (1.f + expf(-y)));
    }
}

// ---------------------------------------------------------------------------
// attention scores: scores[l,b] = (1/64) * dot(r[b], c_history[l,b])
// ---------------------------------------------------------------------------
__global__ void scores_kernel(const float* __restrict__ ch) {
    __shared__ float sh[16];
    const int b = blockIdx.x & 7;
    const float4* r4 = (const float4*)(g_u + (size_t)b * CSP);   // u0 = r
    const float4* c4 = (const float4*)(ch + (size_t)blockIdx.x * CSP);  // blockIdx.x = l*8+b
    float s = 0.f;
    for (int i = threadIdx.x; i < 65536; i += 256) {
        float4 a = r4[i], c = c4[i];
        s += a.x * c.x + a.y * c.y + a.z * c.z + a.w * c.w;
    }
    float dummy = 0.f;
    block_reduce2(s, dummy, sh);
    if (threadIdx.x == 0) g_scores[blockIdx.x] = s * (1.f / 64.f);
}

// softmax over b (axis=0 of [b,l] scores — faithful to source)
__global__ void softmax_kernel() {
    if (threadIdx.x == 0) {
        for (int l = 0; l < 5; ++l) {
            float mx = -1e30f;
            for (int b = 0; b < 8; ++b) mx = fmaxf(mx, g_scores[l * 8 + b]);
            float e[8], sum = 0.f;
            for (int b = 0; b < 8; ++b) { e[b] = expf(g_scores[l * 8 + b] - mx); sum += e[b]; }
            float inv = 1.f / sum;
            for (int b = 0; b < 8; ++b) g_attn[l * 8 + b] = e[b] * inv;
        }
    }
}

// ---------------------------------------------------------------------------
// z = c_history[4] + recall ; write z to out c-slot; per-block LN4 partials
// grid 2048 (b = blk>>8), 256 threads, 4 elems/thread
// ---------------------------------------------------------------------------
__global__ void zstats_kernel(const float* __restrict__ ch, float* __restrict__ out) {
    __shared__ float sh[16];
    const int b = blockIdx.x >> 8;
    const int off = (blockIdx.x & 255) * 1024;
    const float a0 = g_attn[b],      a1 = g_attn[8 + b], a2 = g_attn[16 + b];
    const float a3 = g_attn[24 + b], a4 = 1.f + g_attn[32 + b];
    const float* c0 = ch + (size_t)b * CSP;            // + l*VOL per history step
    float* zc = out + (size_t)4 * VOL + (size_t)b * CSP;
    float s = 0.f, sq = 0.f;
#pragma unroll
    for (int j = 0; j < 4; ++j) {
        int i = off + threadIdx.x + j * 256;
        float z = a0 * c0[i] + a1 * c0[i + VOL] + a2 * c0[i + 2 * VOL]
                + a3 * c0[i + 3 * VOL] + a4 * c0[i + 4 * VOL];
        zc[i] = z; s += z; sq += z * z;
    }
    block_reduce2(s, sq, sh);
    if (threadIdx.x == 0) { g_part[blockIdx.x * 2] = s; g_part[blockIdx.x * 2 + 1] = sq; }
}

// deterministic second-level reduction of LN4 stats (8 blocks, 256 partials each)
__global__ void stats_reduce_kernel() {
    __shared__ float sh[16];
    const int b = blockIdx.x;
    float s  = g_part[(b * 256 + threadIdx.x) * 2];
    float sq = g_part[(b * 256 + threadIdx.x) * 2 + 1];
    block_reduce2(s, sq, sh);
    if (threadIdx.x == 0) { g_stats[b * 2] = s; g_stats[b * 2 + 1] = sq; }
}

// ---------------------------------------------------------------------------
// finalize: c = i*g + LN4(z)*lnw + lnb  (overwrites z in out c-slot)
//           m_new = i'*g' + f'*m       (written to out m-slot)
// ---------------------------------------------------------------------------
__global__ void finalize_kernel(const float* __restrict__ m, const float* __restrict__ lnw,
                                const float* __restrict__ lnb, float* __restrict__ out) {
    const int base = blockIdx.x * 1024;
#pragma unroll
    for (int j = 0; j < 4; ++j) {
        int idx = base + threadIdx.x + j * 256;
        int b = idx >> 18;            // / CSP
        int cs = idx & (CSP - 1);
        float mu = g_stats[2 * b] * (1.f / (float)CSP);
        float var = g_stats[2 * b + 1] * (1.f / (float)CSP) - mu * mu;
        float rstd = rsqrtf(var + EPSF);
        float z = out[4 * VOL + idx];
        float c = g_u[1 * VOL + idx] * g_u[2 * VOL + idx]
                + (z - mu) * rstd * lnw[cs] + lnb[cs];
        float mn = g_u[3 * VOL + idx] * g_u[4 * VOL + idx]
                 + g_u[5 * VOL + idx] * m[idx];
        out[4 * VOL + idx] = c;
        out[5 * VOL + idx] = mn;
    }
}

// ---------------------------------------------------------------------------
// stage5: u6 += conv(c, Wh[7]) + conv(m_new, Wh[8]) + bh[7] + bh[8]
// ---------------------------------------------------------------------------
__global__ void __launch_bounds__(256, 2)
stage5_kernel(const float* __restrict__ out, const float* __restrict__ bh) {
    __shared__ __align__(16) float s_in[1020];
    __shared__ __align__(16) float s_w[1728];
    const int b = blockIdx.z, t0 = blockIdx.y, wbase = blockIdx.x * 8;
    unsigned long long acc[32];
#pragma unroll
    for (int i = 0; i < 32; ++i) acc[i] = 0ull;

    conv_accum(out + (size_t)4 * VOL + (size_t)b * CSP, g_whT + 7 * 110592, 64, t0, wbase, s_in, s_w, acc);
    conv_accum(out + (size_t)5 * VOL + (size_t)b * CSP, g_whT + 8 * 110592, 64, t0, wbase, s_in, s_w, acc);

    const int tid = threadIdx.x;
    const int wl = tid >> 5, hh = tid & 31;
    float* up = g_u + (size_t)6 * VOL + (size_t)b * CSP + t0 * 1024 + (wbase + wl) * 32 + hh;
#pragma unroll
    for (int cp = 0; cp < 32; ++cp) {
        float lo, hi;
        asm("mov.b64 {%0, %1}, %2;" : "=f"(lo), "=f"(hi) : "l"(acc[cp]));
        int co = 2 * cp;
        up[(size_t)co * SP]       += lo + bh[448 + co]     + bh[512 + co];
        up[(size_t)(co + 1) * SP] += hi + bh[448 + co + 1] + bh[512 + co + 1];
    }
}

// ---------------------------------------------------------------------------
// stage7: h_new = o * tanh( w111 @ cat(c, m_new) + b111 )  (1x1x1 conv GEMM)
// ---------------------------------------------------------------------------
__global__ void __launch_bounds__(256, 2)
stage7_kernel(float* __restrict__ out, const float* __restrict__ b111) {
    __shared__ __align__(16) float s_w[8192];     // [128 ci][64 co]
    const int b = blockIdx.z, t0 = blockIdx.y, wbase = blockIdx.x * 8;
    const int tid = threadIdx.x, wl = tid >> 5, hh = tid & 31;
    for (int idx = tid; idx < 8192; idx += 256) s_w[idx] = g_w111T[idx];
    __syncthreads();

    const int pos = t0 * 1024 + (wbase + wl) * 32 + hh;
    const float* cb = out + (size_t)4 * VOL + (size_t)b * CSP + pos;
    const float* mb = out + (size_t)5 * VOL + (size_t)b * CSP + pos;
    unsigned long long acc[32];
#pragma unroll
    for (int i = 0; i < 32; ++i) acc[i] = 0ull;

    for (int half = 0; half < 2; ++half) {
        const float* src = half ? mb : cb;
        for (int ci0 = 0; ci0 < 64; ci0 += 8) {
            float v[8];
#pragma unroll
            for (int j = 0; j < 8; ++j) v[j] = src[(size_t)(ci0 + j) * SP];
#pragma unroll
            for (int j = 0; j < 8; ++j) {
                unsigned long long vv;
                asm("mov.b64 %0, {%1, %1};" : "=l"(vv) : "f"(v[j]));
                const unsigned long long* wq =
                    reinterpret_cast<const unsigned long long*>(s_w + (half * 64 + ci0 + j) * 64);
#pragma unroll
                for (int cp = 0; cp < 32; ++cp)
                    asm("fma.rn.f32x2 %0, %1, %2, %0;" : "+l"(acc[cp]) : "l"(vv), "l"(wq[cp]));
            }
        }
    }

    const float* ob = g_u + (size_t)6 * VOL + (size_t)b * CSP + pos;   // o (post-LN3 sigmoid)
    float* hb = out + (size_t)6 * VOL + (size_t)b * CSP + pos;
#pragma unroll
    for (int cp = 0; cp < 32; ++cp) {
        float lo, hi;
        asm("mov.b64 {%0, %1}, %2;" : "=f"(lo), "=f"(hi) : "l"(acc[cp]));
        int co = 2 * cp;
        hb[(size_t)co * SP]       = ob[(size_t)co * SP]       * tanhf(lo + b111[co]);
        hb[(size_t)(co + 1) * SP] = ob[(size_t)(co + 1) * SP] * tanhf(hi + b111[co + 1]);
    }
}

// ---------------------------------------------------------------------------
// host launcher (graph-capturable: kernels + one async D2D copy only)
// ---------------------------------------------------------------------------
extern "C" void kernel_launch(void* const* d_in, const int* in_sizes, int n_in,
                              void* d_out, int out_size) {
    (void)in_sizes; (void)n_in; (void)out_size;
    const float* x    = (const float*)d_in[0];
    const float* ch   = (const float*)d_in[1];
    const float* m    = (const float*)d_in[2];
    const float* h    = (const float*)d_in[3];
    const float* Wx   = (const float*)d_in[4];
    const float* bx   = (const float*)d_in[5];
    const float* Wh   = (const float*)d_in[6];
    const float* bh   = (const float*)d_in[7];
    const float* w111 = (const float*)d_in[8];
    const float* b111 = (const float*)d_in[9];
    const float* lnw  = (const float*)d_in[10];
    const float* lnb  = (const float*)d_in[11];
    float* out = (float*)d_out;

    prep_kernel<<<4676, 256>>>(Wx, Wh, w111);
    stage1_kernel<<<dim3(4, 4, 56), 256>>>(x, h, m, bx, bh);     // u0..u6 pre-acts
    ln3_act_kernel<<<dim3(512, 6), 256>>>(0);                    // r,i,g,i',g',f'
    scores_kernel<<<40, 256>>>(ch);
    softmax_kernel<<<1, 32>>>();
    zstats_kernel<<<2048, 256>>>(ch, out);                       // z + LN4 partials
    stats_reduce_kernel<<<8, 256>>>();
    finalize_kernel<<<2048, 256>>>(m, lnw, lnb, out);            // c, m_new
    stage5_kernel<<<dim3(4, 4, 8), 256>>>(out, bh);              // u6 += conv(c)+conv(m_new)
    ln3_act_kernel<<<dim3(512, 1), 256>>>(6);                    // o
    stage7_kernel<<<dim3(4, 4, 8), 256>>>(out, b111);            // h_new
    cudaMemcpyAsync(out, ch + VOL, (size_t)4 * VOL * sizeof(float),
                    cudaMemcpyDeviceToDevice);                   // c_history shift
}

// round 13
// speedup vs baseline: 1.3387x; 1.3387x over previous
#include <cuda_runtime.h>
#include <cstdint>

// ---------------------------------------------------------------------------
// Problem constants
//   B=8, CIN=16, HID=64, T=4, W=32, H=32, TAU=5
//   SP  = T*W*H          = 4096
//   CSP = HID*SP         = 262144
//   VOL = B*CSP          = 2097152
// Output layout: c_history_new[5*VOL], m_new[VOL], h_new[VOL]
// ---------------------------------------------------------------------------
#define SP   4096
#define CSP  262144
#define VOL  2097152
#define EPSF 1e-5f

__device__ float g_u[7u * (unsigned)VOL];   // u0..u5 gates, u6 = o-branch
__device__ float g_wxT[7 * 16 * 27 * 64];   // Wx -> [k][ci][tap][co]
__device__ float g_whT[9 * 64 * 27 * 64];   // Wh -> [k][ci][tap][co]
__device__ float g_w111T[128 * 64];         // w111 -> [ci][co]
__device__ float g_spart[640];              // attention score partials
__device__ float g_attn[40];                // [l][b]
__device__ float g_part[2048 * 2];          // LN4 per-block partials
__device__ float g_stats[16];               // LN4 per-b (sum,sumsq)

// ---------------------------------------------------------------------------
// helpers
// ---------------------------------------------------------------------------
__device__ __forceinline__ unsigned long long bcast2(float v) {
    unsigned long long r;
    asm("mov.b64 %0, {%1, %1};" : "=l"(r) : "f"(v));
    return r;
}
__device__ __forceinline__ void ffma2(unsigned long long& a, unsigned long long v,
                                      unsigned long long w) {
    asm("fma.rn.f32x2 %0, %1, %2, %0;" : "+l"(a) : "l"(v), "l"(w));
}
__device__ __forceinline__ void unpack2(unsigned long long a, float& lo, float& hi) {
    asm("mov.b64 {%0, %1}, %2;" : "=f"(lo), "=f"(hi) : "l"(a));
}

__device__ __forceinline__ void block_reduce2(float& a, float& b, float* sh) {
    const int lane = threadIdx.x & 31, wid = threadIdx.x >> 5;
    const int nw = blockDim.x >> 5;
#pragma unroll
    for (int o = 16; o; o >>= 1) {
        a += __shfl_down_sync(0xffffffffu, a, o);
        b += __shfl_down_sync(0xffffffffu, b, o);
    }
    if (lane == 0) { sh[wid] = a; sh[16 + wid] = b; }
    __syncthreads();
    if (wid == 0) {
        a = lane < nw ? sh[lane] : 0.f;
        b = lane < nw ? sh[16 + lane] : 0.f;
#pragma unroll
        for (int o = 8; o; o >>= 1) {
            a += __shfl_down_sync(0xffffffffu, a, o);
            b += __shfl_down_sync(0xffffffffu, b, o);
        }
        if (lane == 0) { sh[0] = a; sh[16] = b; }
    }
    __syncthreads();
    a = sh[0]; b = sh[16];
}

// ---------------------------------------------------------------------------
// Register-blocked 3x3x3 'same' conv accumulation. 512 threads.
// Thread: 2 adjacent w rows x 16 co (8 f32x2 pairs). Block: (b, t0, 8 w rows),
// all 64 co. Per tap: 4x LDS.128 weights reused across both w outputs; per
// (dt,dh): 4 input scalars reused across all dw. LDS wf/FFMA2 ~= 0.33 < 0.5.
// ---------------------------------------------------------------------------
__device__ __forceinline__ void conv_accum512(
    const float* __restrict__ in,   // [CI][4][32][32]
    const float* __restrict__ wT,   // [CI][27][64]
    int CI, int t0, int wbase,
    float* s_in,                    // [3*10*34] = 1020
    float* s_w,                     // [27*64]   = 1728
    unsigned long long acc[2][8])
{
    const int tid = threadIdx.x;
    const int slot = tid & 127;
    const int hh = slot & 31;           // lanes contiguous in h
    const int w0 = (slot >> 5) * 2;     // 0,2,4,6
    const int coq = tid >> 7;           // co quarter 0..3

    for (int ci = 0; ci < CI; ++ci) {
        __syncthreads();   // previous compute done before smem overwrite
        const float* ip = in + ci * SP;
#pragma unroll
        for (int u = 0; u < 2; ++u) {
            int idx = tid + u * 512;
            if (idx < 1020) {
                int dt = idx / 340;
                int rem = idx - dt * 340;
                int row = rem / 34;
                int col = rem - row * 34;
                int tt = t0 + dt - 1, ww = wbase + row - 1, ch = col - 1;
                float v = 0.f;
                if (((unsigned)tt < 4u) & ((unsigned)ww < 32u) & ((unsigned)ch < 32u))
                    v = ip[tt * 1024 + ww * 32 + ch];
                s_in[idx] = v;
            }
        }
        if (tid < 432)
            reinterpret_cast<float4*>(s_w)[tid] =
                reinterpret_cast<const float4*>(wT + ci * 1728)[tid];
        __syncthreads();

#pragma unroll
        for (int dt = 0; dt < 3; ++dt) {
#pragma unroll
            for (int dh = 0; dh < 3; ++dh) {
                float v[4];
#pragma unroll
                for (int r = 0; r < 4; ++r)
                    v[r] = s_in[(dt * 10 + w0 + r) * 34 + hh + dh];
#pragma unroll
                for (int dw = 0; dw < 3; ++dw) {
                    const ulonglong2* wq = reinterpret_cast<const ulonglong2*>(
                        s_w + (dt * 9 + dw * 3 + dh) * 64 + coq * 16);
                    ulonglong2 w01 = wq[0], w23 = wq[1], w45 = wq[2], w67 = wq[3];
                    unsigned long long v0 = bcast2(v[dw]);
                    unsigned long long v1 = bcast2(v[dw + 1]);
                    ffma2(acc[0][0], v0, w01.x); ffma2(acc[0][1], v0, w01.y);
                    ffma2(acc[0][2], v0, w23.x); ffma2(acc[0][3], v0, w23.y);
                    ffma2(acc[0][4], v0, w45.x); ffma2(acc[0][5], v0, w45.y);
                    ffma2(acc[0][6], v0, w67.x); ffma2(acc[0][7], v0, w67.y);
                    ffma2(acc[1][0], v1, w01.x); ffma2(acc[1][1], v1, w01.y);
                    ffma2(acc[1][2], v1, w23.x); ffma2(acc[1][3], v1, w23.y);
                    ffma2(acc[1][4], v1, w45.x); ffma2(acc[1][5], v1, w45.y);
                    ffma2(acc[1][6], v1, w67.x); ffma2(acc[1][7], v1, w67.y);
                }
            }
        }
    }
}

// ---------------------------------------------------------------------------
// prep: weight transposes
// ---------------------------------------------------------------------------
__global__ void prep_kernel(const float* __restrict__ Wx,
                            const float* __restrict__ Wh,
                            const float* __restrict__ w111) {
    int idx = blockIdx.x * 256 + threadIdx.x;
    if (idx < 193536) {                         // Wx: [7][64][16][27] -> [7][16][27][64]
        int co = idx & 63; int q = idx >> 6;
        int tap = q % 27;  int q2 = q / 27;
        int ci = q2 & 15;  int k = q2 >> 4;
        g_wxT[idx] = Wx[((k * 64 + co) * 16 + ci) * 27 + tap];
    } else if (idx < 1188864) {                 // Wh: [9][64][64][27] -> [9][64][27][64]
        int j = idx - 193536;
        int co = j & 63; int q = j >> 6;
        int tap = q % 27; int q2 = q / 27;
        int ci = q2 & 63; int k = q2 >> 6;
        g_whT[j] = Wh[((k * 64 + co) * 64 + ci) * 27 + tap];
    } else if (idx < 1197056) {                 // w111: [64][128] -> [128][64]
        int j = idx - 1188864;
        int co = j & 63; int ci = j >> 6;
        g_w111T[j] = w111[co * 128 + ci];
    }
}

// ---------------------------------------------------------------------------
// stage1: u_k = conv(x,Wx[k]) + conv(state_k,Wh[k]) + biases, k=0..6
// grid (4 wtiles, 4 t, 56 = k*8+b), 512 threads
// ---------------------------------------------------------------------------
__global__ void __launch_bounds__(512, 1)
stage1_kernel(const float* __restrict__ x, const float* __restrict__ h,
              const float* __restrict__ m, const float* __restrict__ bx,
              const float* __restrict__ bh) {
    __shared__ __align__(16) float s_in[1020];
    __shared__ __align__(16) float s_w[1728];
    const int b = blockIdx.z & 7, k = blockIdx.z >> 3;
    const int t0 = blockIdx.y, wbase = blockIdx.x * 8;
    unsigned long long acc[2][8];
#pragma unroll
    for (int e = 0; e < 2; ++e)
#pragma unroll
        for (int p = 0; p < 8; ++p) acc[e][p] = 0ull;

    conv_accum512(x + (size_t)b * 16 * SP, g_wxT + k * 27648, 16, t0, wbase, s_in, s_w, acc);
    const float* st = (k < 3 || k == 6) ? h : m;
    conv_accum512(st + (size_t)b * CSP, g_whT + k * 110592, 64, t0, wbase, s_in, s_w, acc);

    const int tid = threadIdx.x;
    const int slot = tid & 127, hh = slot & 31, w0 = (slot >> 5) * 2, coq = tid >> 7;
    float* up = g_u + (size_t)k * VOL + (size_t)b * CSP + t0 * 1024 + hh;
#pragma unroll
    for (int e = 0; e < 2; ++e) {
        int row = (wbase + w0 + e) * 32;
#pragma unroll
        for (int p = 0; p < 8; ++p) {
            float lo, hi; unpack2(acc[e][p], lo, hi);
            int co = coq * 16 + 2 * p;
            up[(size_t)co * SP + row]       = lo + bx[k * 64 + co]     + bh[k * 64 + co];
            up[(size_t)(co + 1) * SP + row] = hi + bx[k * 64 + co + 1] + bh[k * 64 + co + 1];
        }
    }
}

// ---------------------------------------------------------------------------
// LN3 (per (b,co) over 4096) + activation in place; k in {2,4} -> tanh
// ---------------------------------------------------------------------------
__global__ void ln3_act_kernel(int kbase) {
    __shared__ float sh[32];
    const int k = kbase + blockIdx.y;
    float* buf = g_u + (size_t)k * VOL + (size_t)blockIdx.x * SP;
    const int tid = threadIdx.x;
    float v[16], s = 0.f, sq = 0.f;
#pragma unroll
    for (int j = 0; j < 16; ++j) {
        v[j] = buf[tid + j * 256];
        s += v[j]; sq += v[j] * v[j];
    }
    block_reduce2(s, sq, sh);
    const float mu = s * (1.f / 4096.f);
    const float var = sq * (1.f / 4096.f) - mu * mu;
    const float rstd = rsqrtf(var + EPSF);
    const bool ist = (k == 2 || k == 4);
#pragma unroll
    for (int j = 0; j < 16; ++j) {
        float y = (v[j] - mu) * rstd;
        buf[tid + j * 256] = ist ? tanhf(y) : (1.f / (1.f + expf(-y)));
    }
}

// ---------------------------------------------------------------------------
// attention: partial dot(r[b], c_history[l,b]) over 16 chunks per (l,b)
// ---------------------------------------------------------------------------
__global__ void scores_part_kernel(const float* __restrict__ ch) {
    __shared__ float sh[32];
    const int lb = blockIdx.x >> 4, chunk = blockIdx.x & 15;
    const int b = lb & 7;
    const float4* r4 = (const float4*)(g_u + (size_t)b * CSP) + chunk * 4096;
    const float4* c4 = (const float4*)(ch + (size_t)lb * CSP) + chunk * 4096;
    float s = 0.f;
    for (int i = threadIdx.x; i < 4096; i += 256) {
        float4 a = r4[i], c = c4[i];
        s += a.x * c.x + a.y * c.y + a.z * c.z + a.w * c.w;
    }
    float d = 0.f;
    block_reduce2(s, d, sh);
    if (threadIdx.x == 0) g_spart[blockIdx.x] = s;
}

// reduce partials -> scores[l][b] -> softmax over b per l (faithful to source)
__global__ void scores_softmax_kernel() {
    __shared__ float ssc[40];
    const int t = threadIdx.x;
    if (t < 40) {
        float s = 0.f;
        for (int j = 0; j < 16; ++j) s += g_spart[t * 16 + j];
        ssc[t] = s * (1.f / 64.f);
    }
    __syncthreads();
    if (t < 5) {
        const int l = t;
        float mx = -1e30f;
        for (int b = 0; b < 8; ++b) mx = fmaxf(mx, ssc[l * 8 + b]);
        float e[8], sum = 0.f;
        for (int b = 0; b < 8; ++b) { e[b] = expf(ssc[l * 8 + b] - mx); sum += e[b]; }
        float inv = 1.f / sum;
        for (int b = 0; b < 8; ++b) g_attn[l * 8 + b] = e[b] * inv;
    }
}

// ---------------------------------------------------------------------------
// z = c_history[4] + recall; write to out c-slot; LN4 partial stats
// ---------------------------------------------------------------------------
__global__ void zstats_kernel(const float* __restrict__ ch, float* __restrict__ out) {
    __shared__ float sh[32];
    const int b = blockIdx.x >> 8;
    const int off = (blockIdx.x & 255) * 1024;
    const float a0 = g_attn[b],      a1 = g_attn[8 + b], a2 = g_attn[16 + b];
    const float a3 = g_attn[24 + b], a4 = 1.f + g_attn[32 + b];
    const float* c0 = ch + (size_t)b * CSP;
    float* zc = out + (size_t)4 * VOL + (size_t)b * CSP;
    float s = 0.f, sq = 0.f;
#pragma unroll
    for (int j = 0; j < 4; ++j) {
        int i = off + threadIdx.x + j * 256;
        float z = a0 * c0[i] + a1 * c0[i + VOL] + a2 * c0[i + 2 * VOL]
                + a3 * c0[i + 3 * VOL] + a4 * c0[i + 4 * VOL];
        zc[i] = z; s += z; sq += z * z;
    }
    block_reduce2(s, sq, sh);
    if (threadIdx.x == 0) { g_part[blockIdx.x * 2] = s; g_part[blockIdx.x * 2 + 1] = sq; }
}

__global__ void stats_reduce_kernel() {
    __shared__ float sh[32];
    const int b = blockIdx.x;
    float s  = g_part[(b * 256 + threadIdx.x) * 2];
    float sq = g_part[(b * 256 + threadIdx.x) * 2 + 1];
    block_reduce2(s, sq, sh);
    if (threadIdx.x == 0) { g_stats[b * 2] = s; g_stats[b * 2 + 1] = sq; }
}

// ---------------------------------------------------------------------------
// finalize: c = i*g + LN4(z)*lnw + lnb ; m_new = i'*g' + f'*m
// ---------------------------------------------------------------------------
__global__ void finalize_kernel(const float* __restrict__ m, const float* __restrict__ lnw,
                                const float* __restrict__ lnb, float* __restrict__ out) {
    const int base = blockIdx.x * 1024;
#pragma unroll
    for (int j = 0; j < 4; ++j) {
        int idx = base + threadIdx.x + j * 256;
        int b = idx >> 18;
        int cs = idx & (CSP - 1);
        float mu = g_stats[2 * b] * (1.f / (float)CSP);
        float var = g_stats[2 * b + 1] * (1.f / (float)CSP) - mu * mu;
        float rstd = rsqrtf(var + EPSF);
        float z = out[4 * VOL + idx];
        float c = g_u[1 * VOL + idx] * g_u[2 * VOL + idx]
                + (z - mu) * rstd * lnw[cs] + lnb[cs];
        float mn = g_u[3 * VOL + idx] * g_u[4 * VOL + idx]
                 + g_u[5 * VOL + idx] * m[idx];
        out[4 * VOL + idx] = c;
        out[5 * VOL + idx] = mn;
    }
}

// ---------------------------------------------------------------------------
// stage5: u6 += conv(c,Wh[7]) + conv(m_new,Wh[8]) + bh[7] + bh[8]
// ---------------------------------------------------------------------------
__global__ void __launch_bounds__(512, 1)
stage5_kernel(const float* __restrict__ out, const float* __restrict__ bh) {
    __shared__ __align__(16) float s_in[1020];
    __shared__ __align__(16) float s_w[1728];
    const int b = blockIdx.z, t0 = blockIdx.y, wbase = blockIdx.x * 8;
    unsigned long long acc[2][8];
#pragma unroll
    for (int e = 0; e < 2; ++e)
#pragma unroll
        for (int p = 0; p < 8; ++p) acc[e][p] = 0ull;

    conv_accum512(out + (size_t)4 * VOL + (size_t)b * CSP, g_whT + 7 * 110592, 64,
                  t0, wbase, s_in, s_w, acc);
    conv_accum512(out + (size_t)5 * VOL + (size_t)b * CSP, g_whT + 8 * 110592, 64,
                  t0, wbase, s_in, s_w, acc);

    const int tid = threadIdx.x;
    const int slot = tid & 127, hh = slot & 31, w0 = (slot >> 5) * 2, coq = tid >> 7;
    float* up = g_u + (size_t)6 * VOL + (size_t)b * CSP + t0 * 1024 + hh;
#pragma unroll
    for (int e = 0; e < 2; ++e) {
        int row = (wbase + w0 + e) * 32;
#pragma unroll
        for (int p = 0; p < 8; ++p) {
            float lo, hi; unpack2(acc[e][p], lo, hi);
            int co = coq * 16 + 2 * p;
            up[(size_t)co * SP + row]       += lo + bh[448 + co]     + bh[512 + co];
            up[(size_t)(co + 1) * SP + row] += hi + bh[448 + co + 1] + bh[512 + co + 1];
        }
    }
}

// ---------------------------------------------------------------------------
// stage7: h_new = o * tanh( w111 @ cat(c, m_new) + b111 )
// ---------------------------------------------------------------------------
__global__ void __launch_bounds__(256, 2)
stage7_kernel(float* __restrict__ out, const float* __restrict__ b111) {
    __shared__ __align__(16) float s_w[8192];     // [128 ci][64 co]
    const int b = blockIdx.z, t0 = blockIdx.y, wbase = blockIdx.x * 8;
    const int tid = threadIdx.x, wl = tid >> 5, hh = tid & 31;
    for (int idx = tid; idx < 2048; idx += 256)
        reinterpret_cast<float4*>(s_w)[idx] = reinterpret_cast<const float4*>(g_w111T)[idx];
    __syncthreads();

    const int pos = t0 * 1024 + (wbase + wl) * 32 + hh;
    const float* cb = out + (size_t)4 * VOL + (size_t)b * CSP + pos;
    const float* mb = out + (size_t)5 * VOL + (size_t)b * CSP + pos;
    unsigned long long acc[32];
#pragma unroll
    for (int i = 0; i < 32; ++i) acc[i] = 0ull;

    for (int half = 0; half < 2; ++half) {
        const float* src = half ? mb : cb;
        for (int ci0 = 0; ci0 < 64; ci0 += 8) {
            float v[8];
#pragma unroll
            for (int j = 0; j < 8; ++j) v[j] = src[(size_t)(ci0 + j) * SP];
#pragma unroll
            for (int j = 0; j < 8; ++j) {
                unsigned long long vv = bcast2(v[j]);
                const ulonglong2* wq = reinterpret_cast<const ulonglong2*>(
                    s_w + (half * 64 + ci0 + j) * 64);
#pragma unroll
                for (int q = 0; q < 16; ++q) {
                    ulonglong2 wp = wq[q];
                    ffma2(acc[2 * q], vv, wp.x);
                    ffma2(acc[2 * q + 1], vv, wp.y);
                }
            }
        }
    }

    const float* ob = g_u + (size_t)6 * VOL + (size_t)b * CSP + pos;
    float* hb = out + (size_t)6 * VOL + (size_t)b * CSP + pos;
#pragma unroll
    for (int cp = 0; cp < 32; ++cp) {
        float lo, hi; unpack2(acc[cp], lo, hi);
        int co = 2 * cp;
        hb[(size_t)co * SP]       = ob[(size_t)co * SP]       * tanhf(lo + b111[co]);
        hb[(size_t)(co + 1) * SP] = ob[(size_t)(co + 1) * SP] * tanhf(hi + b111[co + 1]);
    }
}

// ---------------------------------------------------------------------------
// host launcher
// ---------------------------------------------------------------------------
extern "C" void kernel_launch(void* const* d_in, const int* in_sizes, int n_in,
                              void* d_out, int out_size) {
    (void)in_sizes; (void)n_in; (void)out_size;
    const float* x    = (const float*)d_in[0];
    const float* ch   = (const float*)d_in[1];
    const float* m    = (const float*)d_in[2];
    const float* h    = (const float*)d_in[3];
    const float* Wx   = (const float*)d_in[4];
    const float* bx   = (const float*)d_in[5];
    const float* Wh   = (const float*)d_in[6];
    const float* bh   = (const float*)d_in[7];
    const float* w111 = (const float*)d_in[8];
    const float* b111 = (const float*)d_in[9];
    const float* lnw  = (const float*)d_in[10];
    const float* lnb  = (const float*)d_in[11];
    float* out = (float*)d_out;

    prep_kernel<<<4676, 256>>>(Wx, Wh, w111);
    stage1_kernel<<<dim3(4, 4, 56), 512>>>(x, h, m, bx, bh);     // u0..u6 pre-acts
    ln3_act_kernel<<<dim3(512, 6), 256>>>(0);                    // r,i,g,i',g',f'
    scores_part_kernel<<<640, 256>>>(ch);
    scores_softmax_kernel<<<1, 64>>>();
    zstats_kernel<<<2048, 256>>>(ch, out);                       // z + LN4 partials
    stats_reduce_kernel<<<8, 256>>>();
    finalize_kernel<<<2048, 256>>>(m, lnw, lnb, out);            // c, m_new
    stage5_kernel<<<dim3(4, 4, 8), 512>>>(out, bh);              // u6 += conv(c)+conv(m_new)
    ln3_act_kernel<<<dim3(512, 1), 256>>>(6);                    // o
    stage7_kernel<<<dim3(4, 4, 8), 256>>>(out, b111);            // h_new
    cudaMemcpyAsync(out, ch + VOL, (size_t)4 * VOL * sizeof(float),
                    cudaMemcpyDeviceToDevice);                   // c_history shift
}